// round 2
// baseline (speedup 1.0000x reference)
#include <cuda_runtime.h>

// Problem constants
#define BB   64
#define TT   512
#define DH   1024
#define RNK  16

// ---------------- device scratch (static, allocation-free) ----------------
__device__ float g_Gin_ih[1024 * 16];   // [j][d]
__device__ float g_Gin_hh[1024 * 16];   // [j][d]
__device__ float g_G56_ih[16 * 256];    // [e][mp]
__device__ float g_G56_hh[16 * 256];    // [e][mp]
__device__ float g_bias4[4096];         // [j][gate] (b_ih + b_hh, reindexed)
__device__ float g_ihg[(size_t)BB * TT * 4096]; // [b][t][j][gate]  (512 MB)

// ---------------- fast activations (ex2/rcp approx, ~1e-6 accurate) -------
__device__ __forceinline__ float fexp2(float x) {
    float y; asm("ex2.approx.f32 %0, %1;" : "=f"(y) : "f"(x)); return y;
}
__device__ __forceinline__ float frcp(float x) {
    float y; asm("rcp.approx.f32 %0, %1;" : "=f"(y) : "f"(x)); return y;
}
// sigmoid(x) = 1/(1+2^(-x*log2e)); robust at +/-inf
__device__ __forceinline__ float sigmoidf(float x) {
    return frcp(1.0f + fexp2(-1.4426950408889634f * x));
}
// tanh(x) = 2*sigmoid(2x) - 1; robust at +/-inf
__device__ __forceinline__ float tanhf_(float x) {
    return fmaf(2.0f, frcp(1.0f + fexp2(-2.8853900817779268f * x)), -1.0f);
}

// ---------------- kernel 0: build contraction tables ----------------------
// Gin[(i,j,k)][d] = sum_{a,c} g1[i,a] g2[a,j,c] g3[c,k,d]
// G56[e][m*16+p]  = sum_f g5[e,m,f] g6[f,p]
__global__ void k_build(const float* g1i, const float* g2i, const float* g3i,
                        const float* g5i, const float* g6i,
                        const float* g1h, const float* g2h, const float* g3h,
                        const float* g5h, const float* g6h,
                        const float* bih, const float* bhh)
{
    __shared__ float G12[1024]; // [i][j][c]  (8*8*16)
    int tid = threadIdx.x;      // 1024 threads

    #pragma unroll
    for (int path = 0; path < 2; path++) {
        const float* g1 = path ? g1h : g1i;
        const float* g2 = path ? g2h : g2i;
        const float* g3 = path ? g3h : g3i;
        const float* g5 = path ? g5h : g5i;
        const float* g6 = path ? g6h : g6i;
        float* Gin = path ? g_Gin_hh : g_Gin_ih;
        float* G56 = path ? g_G56_hh : g_G56_ih;

        { // G12[i][j][c]
            int i = tid >> 7, j = (tid >> 4) & 7, c = tid & 15;
            float s = 0.f;
            #pragma unroll
            for (int a = 0; a < 16; a++)
                s = fmaf(g1[i * 16 + a], g2[a * 128 + j * 16 + c], s);
            G12[tid] = s;
        }
        __syncthreads();
        // Gin: 1024 rows x 16 d
        for (int o = tid; o < 16384; o += 1024) {
            int row = o >> 4, d = o & 15;
            int i = row >> 7, j = (row >> 4) & 7, k = row & 15;
            float s = 0.f;
            #pragma unroll
            for (int c = 0; c < 16; c++)
                s = fmaf(G12[i * 128 + j * 16 + c], g3[c * 256 + k * 16 + d], s);
            Gin[row * 16 + d] = s;
        }
        // G56: 16 e x 256 mp
        for (int o = tid; o < 4096; o += 1024) {
            int e = o >> 8, m = (o >> 4) & 15, p = o & 15;
            float s = 0.f;
            #pragma unroll
            for (int f = 0; f < 16; f++)
                s = fmaf(g5[e * 256 + m * 16 + f], g6[f * 16 + p], s);
            G56[o] = s;
        }
        __syncthreads(); // G12 reused next path
    }
    // bias reindexed to [j][gate]
    {
        int j = tid;
        float4 v;
        v.x = bih[j]        + bhh[j];
        v.y = bih[1024 + j] + bhh[1024 + j];
        v.z = bih[2048 + j] + bhh[2048 + j];
        v.w = bih[3072 + j] + bhh[3072 + j];
        ((float4*)g_bias4)[j] = v;
    }
}

// ---------------- kernel 1: precompute ih gates for all (b,t) -------------
// one block (256 thr) per row rb = b*512 + t
__global__ void __launch_bounds__(256) k_pre(const float* __restrict__ x,
                                             const float* __restrict__ g4i)
{
    __shared__ float xs[1024];
    __shared__ float pp[16][17];
    __shared__ float ihp[16];
    __shared__ float A[256]; // [n][e]

    int rb  = blockIdx.x;
    int tid = threadIdx.x;

    ((float4*)xs)[tid] = ((const float4*)(x + (size_t)rb * 1024))[tid];
    __syncthreads();

    { // ihp[d] = sum_j xs[j] * Gin_ih[j][d]   (split: 16 chunks of 64)
        int d = tid & 15, ch = tid >> 4;
        const float* gp = g_Gin_ih + (ch * 64) * 16 + d;
        const float* xp = xs + ch * 64;
        float s = 0.f;
        #pragma unroll
        for (int u = 0; u < 64; u++) s = fmaf(xp[u], gp[u * 16], s);
        pp[ch][d] = s;
    }
    __syncthreads();
    if (tid < 16) {
        float s = 0.f;
        #pragma unroll
        for (int c2 = 0; c2 < 16; c2++) s += pp[c2][tid];
        ihp[tid] = s;
    }
    __syncthreads();
    { // A[n][e] = sum_d ihp[d] * g4_ih[d][n][e]
        int n = tid >> 4, e = tid & 15;
        float s = 0.f;
        #pragma unroll
        for (int d = 0; d < 16; d++)
            s = fmaf(ihp[d], __ldg(g4i + d * 256 + n * 16 + e), s);
        A[tid] = s;
    }
    __syncthreads();
    // stage2: mp = tid; outputs j = k*256 + tid, gates 0..3
    float G[16];
    #pragma unroll
    for (int e = 0; e < 16; e++) G[e] = g_G56_ih[e * 256 + tid];

    float* outp = g_ihg + (size_t)rb * 4096;
    #pragma unroll
    for (int k = 0; k < 4; k++) {
        int j = k * 256 + tid;
        float4 bv = ((const float4*)g_bias4)[j];
        float acc0 = 0.f, acc1 = 0.f, acc2 = 0.f, acc3 = 0.f;
        #pragma unroll
        for (int e = 0; e < 16; e++) {
            acc0 = fmaf(A[(0 * 4 + k) * 16 + e], G[e], acc0);
            acc1 = fmaf(A[(1 * 4 + k) * 16 + e], G[e], acc1);
            acc2 = fmaf(A[(2 * 4 + k) * 16 + e], G[e], acc2);
            acc3 = fmaf(A[(3 * 4 + k) * 16 + e], G[e], acc3);
        }
        float4 v;
        v.x = acc0 + bv.x; v.y = acc1 + bv.y;
        v.z = acc2 + bv.z; v.w = acc3 + bv.w;
        ((float4*)outp)[j] = v;
    }
}

// ---------------- kernel 2: recurrence, one CTA per batch element --------
__global__ void __launch_bounds__(1024, 1) k_rec(const float* __restrict__ g4h,
                                                 float* __restrict__ out)
{
    __shared__ float g4sh[4096];   // [d][n][e]
    __shared__ float G56sh[4096];  // [e][mp]
    __shared__ float Ash[256];     // [n][e]
    __shared__ float Psh[16];
    __shared__ float pp[32][17];

    int tid = threadIdx.x;
    int b   = blockIdx.x;
    const unsigned FULL = 0xffffffffu;

    for (int i = tid; i < 4096; i += 1024) {
        g4sh[i]  = g4h[i];
        G56sh[i] = g_G56_hh[i];
    }

    // per-thread constants
    int q  = tid & 15;          // d handled in phase-1
    int jb = tid & ~15;         // 16-group base
    float Gr[16];
    #pragma unroll
    for (int u = 0; u < 16; u++) Gr[u] = g_Gin_hh[(jb + u) * 16 + q];

    int mp = tid & 255, nb = tid >> 8;
    int warp = tid >> 5;

    float h = 0.f, c = 0.f;
    const float* ihp_ptr = g_ihg + (size_t)b * TT * 4096 + (size_t)tid * 4;
    float4 ihg = *(const float4*)ihp_ptr; // t = 0
    float* outb = out + (size_t)b * TT * DH;

    __syncthreads(); // tables + Gr source ready (Gr from global, fine; tables for loop)

    for (int t = 0; t < TT; t++) {
        // ---- phase 1: P[d] = sum_j h[j] * Gin_hh[j][d] ----
        float part = 0.f;
        #pragma unroll
        for (int u = 0; u < 16; u++) {
            float hu = __shfl_sync(FULL, h, u, 16); // within 16-lane group
            part = fmaf(hu, Gr[u], part);
        }
        part += __shfl_xor_sync(FULL, part, 16);    // fold warp's two groups
        if ((tid & 31) < 16) pp[warp][q] = part;
        __syncthreads();                            // BAR1
        if (tid < 32) {
            int d = tid & 15, half = tid >> 4;
            float s = 0.f;
            #pragma unroll
            for (int w = 0; w < 16; w++) s += pp[half * 16 + w][d];
            s += __shfl_xor_sync(FULL, s, 16);
            if (tid < 16) Psh[tid] = s;
        }
        __syncthreads();                            // BAR2
        // ---- stage 1: A[n][e] = sum_d P[d] * g4[d][n][e] ----
        if (tid < 256) {
            int n = tid >> 4, e = tid & 15;
            float s = 0.f;
            #pragma unroll
            for (int d = 0; d < 16; d++)
                s = fmaf(Psh[d], g4sh[d * 256 + n * 16 + e], s);
            Ash[tid] = s;
        }
        // prefetch next timestep's ih gates while waiting
        float4 ihg_n = make_float4(0.f, 0.f, 0.f, 0.f);
        if (t < TT - 1)
            ihg_n = *(const float4*)(ihp_ptr + (size_t)(t + 1) * 4096);
        __syncthreads();                            // BAR3
        // ---- stage 2: gates[g] = sum_e A[g*4+nb][e] * G56[e][mp] + ih ----
        float G[16];
        #pragma unroll
        for (int e = 0; e < 16; e++) G[e] = G56sh[e * 256 + mp];

        float a0 = ihg.x, a1 = ihg.y, a2 = ihg.z, a3 = ihg.w;
        {
            const float* Ar0 = Ash + (0 * 4 + nb) * 16;
            const float* Ar1 = Ash + (1 * 4 + nb) * 16;
            const float* Ar2 = Ash + (2 * 4 + nb) * 16;
            const float* Ar3 = Ash + (3 * 4 + nb) * 16;
            #pragma unroll
            for (int e = 0; e < 16; e++) {
                a0 = fmaf(Ar0[e], G[e], a0);
                a1 = fmaf(Ar1[e], G[e], a1);
                a2 = fmaf(Ar2[e], G[e], a2);
                a3 = fmaf(Ar3[e], G[e], a3);
            }
        }
        // ---- LSTM cell ----
        float si = sigmoidf(a0);
        float sf = sigmoidf(a1);
        float tg = tanhf_(a2);
        float so = sigmoidf(a3);
        c = sf * c + si * tg;
        h = so * tanhf_(c);

        outb[(size_t)t * DH + tid] = h;
        ihg = ihg_n;
    }

    // final (h, c) appended after output tensor
    float* hc = out + (size_t)BB * TT * DH;
    hc[b * DH + tid] = h;
    hc[(size_t)BB * DH + b * DH + tid] = c;
}

// ---------------- launcher -------------------------------------------------
extern "C" void kernel_launch(void* const* d_in, const int* in_sizes, int n_in,
                              void* d_out, int out_size)
{
    const float* x    = (const float*)d_in[0];
    const float* ih1  = (const float*)d_in[1];
    const float* ih2  = (const float*)d_in[2];
    const float* ih3  = (const float*)d_in[3];
    const float* ih4  = (const float*)d_in[4];
    const float* ih5  = (const float*)d_in[5];
    const float* ih6  = (const float*)d_in[6];
    const float* hh1  = (const float*)d_in[7];
    const float* hh2  = (const float*)d_in[8];
    const float* hh3  = (const float*)d_in[9];
    const float* hh4  = (const float*)d_in[10];
    const float* hh5  = (const float*)d_in[11];
    const float* hh6  = (const float*)d_in[12];
    const float* bih  = (const float*)d_in[13];
    const float* bhh  = (const float*)d_in[14];
    float* out = (float*)d_out;

    k_build<<<1, 1024>>>(ih1, ih2, ih3, ih5, ih6,
                         hh1, hh2, hh3, hh5, hh6, bih, bhh);
    k_pre<<<BB * TT, 256>>>(x, ih4);
    k_rec<<<BB, 1024>>>(hh4, out);
}